// round 2
// baseline (speedup 1.0000x reference)
#include <cuda_runtime.h>

// Problem constants
#define BB   2
#define SS   2048
#define HH   16
#define DK   64
#define DM   1024
#define MM   (BB*SS)                 // 4096 rows of x
#define OUT_ELEMS  (4194304)         // B*S*DM
#define ATTN_ELEMS (134217728)       // B*H*S*S

// Scratch (allocation-free rule: device globals)
__device__ float g_q [BB*HH*SS*DK];   // [bh][s][d]
__device__ float g_k [BB*HH*SS*DK];
__device__ float g_v [BB*HH*SS*DK];
__device__ float g_ao[MM*DM];         // attn_out, (b,s,h,d) flat [4096][1024]

// ---------------------------------------------------------------------------
// NT GEMM: C = scale * (A @ B^T) (+bias). A:[M,K] row-major, B:[N,K] row-major.
// 128x128 block tile, 8x8 micro tile, BK=8, 256 threads. Batched via blockIdx.z.
// headstore: scatter C[m,n] into head-major [b,h,s,d] layout (for q/k/v proj).
// ---------------------------------------------------------------------------
__global__ void __launch_bounds__(256, 2) gemm_nt(
    const float* __restrict__ A, const float* __restrict__ Bm,
    const float* __restrict__ bias, float* __restrict__ C,
    int K, int N, long long sA, long long sB, long long sC,
    float scale, int headstore)
{
    __shared__ float As[8][128];
    __shared__ float Bs[8][128];

    A  += (long long)blockIdx.z * sA;
    Bm += (long long)blockIdx.z * sB;
    C  += (long long)blockIdx.z * sC;

    const int tid = threadIdx.x;
    const int m0 = blockIdx.y * 128;
    const int n0 = blockIdx.x * 128;

    const int lr = tid >> 1;            // 0..127 tile row for loads
    const int lk = (tid & 1) << 2;      // 0 or 4
    const int rb = (tid >> 4) << 3;     // micro-tile row base
    const int cb = (tid & 15) << 3;     // micro-tile col base

    float acc[8][8];
    #pragma unroll
    for (int i = 0; i < 8; i++)
        #pragma unroll
        for (int j = 0; j < 8; j++) acc[i][j] = 0.f;

    const float* Ap = A  + (long long)(m0 + lr) * K + lk;
    const float* Bp = Bm + (long long)(n0 + lr) * K + lk;

    for (int k0 = 0; k0 < K; k0 += 8) {
        float4 av = *(const float4*)(Ap + k0);
        float4 bv = *(const float4*)(Bp + k0);
        __syncthreads();
        As[lk+0][lr] = av.x; As[lk+1][lr] = av.y; As[lk+2][lr] = av.z; As[lk+3][lr] = av.w;
        Bs[lk+0][lr] = bv.x; Bs[lk+1][lr] = bv.y; Bs[lk+2][lr] = bv.z; Bs[lk+3][lr] = bv.w;
        __syncthreads();

        #pragma unroll
        for (int kk = 0; kk < 8; kk++) {
            float4 a0 = *(const float4*)&As[kk][rb];
            float4 a1 = *(const float4*)&As[kk][rb + 4];
            float4 b0 = *(const float4*)&Bs[kk][cb];
            float4 b1 = *(const float4*)&Bs[kk][cb + 4];
            float a[8] = {a0.x,a0.y,a0.z,a0.w,a1.x,a1.y,a1.z,a1.w};
            float b[8] = {b0.x,b0.y,b0.z,b0.w,b1.x,b1.y,b1.z,b1.w};
            #pragma unroll
            for (int i = 0; i < 8; i++)
                #pragma unroll
                for (int j = 0; j < 8; j++)
                    acc[i][j] = fmaf(a[i], b[j], acc[i][j]);
        }
    }

    #pragma unroll
    for (int i = 0; i < 8; i++) {
        const int m = m0 + rb + i;
        #pragma unroll
        for (int j = 0; j < 8; j++) {
            const int n = n0 + cb + j;
            float v = acc[i][j] * scale;
            if (bias) v += bias[n];
            if (headstore) {
                // b = m>>11, s = m&2047, h = n>>6, d = n&63
                long long idx = (((long long)((m >> 11) * HH + (n >> 6))) * SS + (m & (SS-1))) * DK + (n & (DK-1));
                C[idx] = v;
            } else {
                C[(long long)m * N + n] = v;
            }
        }
    }
}

// ---------------------------------------------------------------------------
// NN GEMM: attn_out[bh][q,d] = sum_k P[bh][q,k] * V[bh][k,d]
// M=2048 (q), N=64 (d), K=2048. 128x64 block tile, 8x4 micro, BK=16.
// Output scattered to (b,s,h,d) flat layout.
// ---------------------------------------------------------------------------
__global__ void __launch_bounds__(256, 2) gemm_av(
    const float* __restrict__ P, const float* __restrict__ V, float* __restrict__ out)
{
    __shared__ float As[16][128];
    __shared__ float Bs[16][64];

    const int bh = blockIdx.z;
    const int b = bh >> 4, h = bh & 15;
    const float* A  = P + (long long)bh * SS * SS;
    const float* Bv = V + (long long)bh * SS * DK;
    const int q0 = blockIdx.x * 128;
    const int tid = threadIdx.x;

    const int ar0 = tid >> 2;            // 0..63 (rows ar0 and ar0+64)
    const int ak0 = (tid & 3) << 2;      // 0,4,8,12
    const int bk  = tid >> 4;            // 0..15
    const int bn  = (tid & 15) << 2;     // 0..60
    const int rb  = (tid >> 4) << 3;     // micro row base 0..120
    const int cb  = (tid & 15) << 2;     // micro col base 0..60

    float acc[8][4];
    #pragma unroll
    for (int i = 0; i < 8; i++)
        #pragma unroll
        for (int j = 0; j < 4; j++) acc[i][j] = 0.f;

    for (int k0 = 0; k0 < SS; k0 += 16) {
        float4 a0 = *(const float4*)(A + (long long)(q0 + ar0)      * SS + k0 + ak0);
        float4 a1 = *(const float4*)(A + (long long)(q0 + ar0 + 64) * SS + k0 + ak0);
        float4 b0 = *(const float4*)(Bv + (long long)(k0 + bk) * DK + bn);
        __syncthreads();
        As[ak0+0][ar0] = a0.x; As[ak0+1][ar0] = a0.y; As[ak0+2][ar0] = a0.z; As[ak0+3][ar0] = a0.w;
        As[ak0+0][ar0+64] = a1.x; As[ak0+1][ar0+64] = a1.y; As[ak0+2][ar0+64] = a1.z; As[ak0+3][ar0+64] = a1.w;
        *(float4*)&Bs[bk][bn] = b0;
        __syncthreads();

        #pragma unroll
        for (int kk = 0; kk < 16; kk++) {
            float4 a0v = *(const float4*)&As[kk][rb];
            float4 a1v = *(const float4*)&As[kk][rb + 4];
            float4 bv4 = *(const float4*)&Bs[kk][cb];
            float a[8] = {a0v.x,a0v.y,a0v.z,a0v.w,a1v.x,a1v.y,a1v.z,a1v.w};
            float bt[4] = {bv4.x,bv4.y,bv4.z,bv4.w};
            #pragma unroll
            for (int i = 0; i < 8; i++)
                #pragma unroll
                for (int j = 0; j < 4; j++)
                    acc[i][j] = fmaf(a[i], bt[j], acc[i][j]);
        }
    }

    #pragma unroll
    for (int i = 0; i < 8; i++) {
        const int q = q0 + rb + i;
        #pragma unroll
        for (int j = 0; j < 4; j++) {
            const int d = cb + j;
            out[((long long)(b * SS + q)) * DM + h * DK + d] = acc[i][j];
        }
    }
}

// ---------------------------------------------------------------------------
// Sparsemax (in-place per row of 2048). One block (256 thr) per row.
// ---------------------------------------------------------------------------
template<int OP> // 0=sum, 1=max
__device__ __forceinline__ float blockReduce(float v, float* sh)
{
    const int tid = threadIdx.x, l = tid & 31, w = tid >> 5;
    #pragma unroll
    for (int o = 16; o; o >>= 1) {
        float u = __shfl_xor_sync(0xffffffffu, v, o);
        v = OP ? fmaxf(v, u) : v + u;
    }
    if (l == 0) sh[w] = v;
    __syncthreads();
    if (tid < 32) {
        v = (l < 8) ? sh[l] : (OP ? -1e30f : 0.f);
        #pragma unroll
        for (int o = 4; o; o >>= 1) {
            float u = __shfl_xor_sync(0xffffffffu, v, o);
            v = OP ? fmaxf(v, u) : v + u;
        }
        if (l == 0) sh[0] = v;
    }
    __syncthreads();
    float r = sh[0];
    __syncthreads();
    return r;
}

__global__ void __launch_bounds__(256) sparsemax_kernel(float* __restrict__ attn)
{
    __shared__ float sh[32];
    float* z = attn + (long long)blockIdx.x * SS;
    const int tid = threadIdx.x;

    float v[8];
    #pragma unroll
    for (int i = 0; i < 8; i++) v[i] = z[tid + i * 256];

    float mx = -1e30f;
    #pragma unroll
    for (int i = 0; i < 8; i++) mx = fmaxf(mx, v[i]);
    mx = blockReduce<1>(mx, sh);

    // Bisection on f(tau) = sum(max(z - tau, 0)); tau* in [mx-1, mx]
    float lo = mx - 1.f, hi = mx;
    for (int it = 0; it < 20; it++) {
        float mid = 0.5f * (lo + hi);
        float s = 0.f;
        #pragma unroll
        for (int i = 0; i < 8; i++) s += fmaxf(v[i] - mid, 0.f);
        s = blockReduce<0>(s, sh);
        if (s >= 1.f) lo = mid; else hi = mid;
    }

    // Michelot refinement from a lower bound: converges to exact tau*
    float tau = lo;
    for (int it = 0; it < 6; it++) {
        float s = 0.f, c = 0.f;
        #pragma unroll
        for (int i = 0; i < 8; i++)
            if (v[i] > tau) { s += v[i]; c += 1.f; }
        s = blockReduce<0>(s, sh);
        c = blockReduce<0>(c, sh);
        tau = (s - 1.f) / c;   // c >= 1 always (row max is in support)
    }

    #pragma unroll
    for (int i = 0; i < 8; i++) z[tid + i * 256] = fmaxf(v[i] - tau, 0.f);
}

// ---------------------------------------------------------------------------
extern "C" void kernel_launch(void* const* d_in, const int* in_sizes, int n_in,
                              void* d_out, int out_size)
{
    const float* query = (const float*)d_in[0];
    const float* key   = (const float*)d_in[1];
    const float* value = (const float*)d_in[2];
    const float* Wq = (const float*)d_in[3];  const float* bq = (const float*)d_in[4];
    const float* Wk = (const float*)d_in[5];  const float* bk = (const float*)d_in[6];
    const float* Wv = (const float*)d_in[7];  const float* bv = (const float*)d_in[8];
    const float* Wfc = (const float*)d_in[9]; const float* bfc = (const float*)d_in[10];

    float* out  = (float*)d_out;
    float* attn = out + OUT_ELEMS;   // attention output lives in d_out after 'output'

    float *pq, *pk, *pv, *pao;
    cudaGetSymbolAddress((void**)&pq,  g_q);
    cudaGetSymbolAddress((void**)&pk,  g_k);
    cudaGetSymbolAddress((void**)&pv,  g_v);
    cudaGetSymbolAddress((void**)&pao, g_ao);

    // 1) Projections -> head-major q/k/v
    gemm_nt<<<dim3(DM/128, MM/128, 1), 256>>>(query, Wq, bq, pq, DM, DM, 0, 0, 0, 1.f, 1);
    gemm_nt<<<dim3(DM/128, MM/128, 1), 256>>>(key,   Wk, bk, pk, DM, DM, 0, 0, 0, 1.f, 1);
    gemm_nt<<<dim3(DM/128, MM/128, 1), 256>>>(value, Wv, bv, pv, DM, DM, 0, 0, 0, 1.f, 1);

    // 2) logits = q @ k^T / 8 -> attention slice of d_out (batched over 32 heads)
    gemm_nt<<<dim3(SS/128, SS/128, BB*HH), 256>>>(
        pq, pk, nullptr, attn, DK, SS,
        (long long)SS*DK, (long long)SS*DK, (long long)SS*SS, 0.125f, 0);

    // 3) sparsemax in place (also finalizes the attention output)
    sparsemax_kernel<<<BB*HH*SS, 256>>>(attn);

    // 4) attn_out = P @ V -> (b,s,h,d) flat
    gemm_av<<<dim3(SS/128, 1, BB*HH), 256>>>(attn, pv, pao);

    // 5) output = attn_out @ Wfc^T + bfc -> d_out[0:OUT_ELEMS]
    gemm_nt<<<dim3(DM/128, MM/128, 1), 256>>>(pao, Wfc, bfc, out, DM, DM, 0, 0, 0, 1.f, 0);
}